// round 14
// baseline (speedup 1.0000x reference)
#include <cuda_runtime.h>
#include <math.h>

// PerformanceModel_4346506903896
// out[i] = prod_j sigmoid( (ub[j] - logit(bin_centers[idx[i][j]])) / (ub[j]-lb[j]+1e-4) )
//
// R14 (= R12 resubmitted after infra failure; kernel never ran):
//   bank-spread LUT replication x2 to cut LDS gather conflicts.
//   tab[j] entries stored twice: word 2*idx + p, lane uses p = lane&1.
//   Even lanes gather from even banks, odd lanes from odd banks -> two
//   parallel 16-over-16 conflict problems instead of one 32-over-32:
//   E[wavefronts/gather] ~3.3 -> ~2.8. Everything else as R11
//   (1184 blocks x 256 thr, 8 CTAs/SM, 2 groups/iter, 6 front-batched
//   LDG.128 at 48B lane stride, in-block MUFU LUT init).
//
// Inputs (metadata order):
//   d_in[0]: bin_centers  float32 [1024]
//   d_in[1]: indices      int32   [16777216, 3]
//   d_in[2]: lb           float32 [3]
//   d_in[3]: ub           float32 [3]
//   d_in[4]: operator_number (unused by the math)
// Output: float32 [16777216]

#define N_BINS   1024
#define BLOCK    256
#define GRID     1184                       // 148 SMs x 8 CTAs
#define N_GROUPS 4194304LL                  // 16,777,216 rows / 4
#define N_PAIRS  (N_GROUPS / 2)             // 2,097,152

__global__ __launch_bounds__(BLOCK, 8)
void pm_kernel(const float* __restrict__ bin_centers,
               const int4*  __restrict__ idx4,
               const float* __restrict__ lb,
               const float* __restrict__ ub,
               float4*      __restrict__ out4)
{
    // 24 KB: each table entry duplicated at adjacent words (even/odd bank).
    __shared__ float tab[3 * 2 * N_BINS];

    const int tid = threadIdx.x;

    // ---- LUT init: 4 logits/thread, 12 entries/thread x2 copies, all MUFU --
    {
        float lg[4];
        #pragma unroll
        for (int k = 0; k < 4; ++k) {
            float c = bin_centers[k * BLOCK + tid];
            lg[k] = __logf(__fdividef(c, 1.0f - c));   // finite: c in (0.01,0.99)
        }
        #pragma unroll
        for (int j = 0; j < 3; ++j) {
            float u  = ub[j];
            float iv = __fdividef(1.0f, u - lb[j] + 1e-4f);
            #pragma unroll
            for (int k = 0; k < 4; ++k) {
                float x = (u - lg[k]) * iv;
                float s = __fdividef(1.0f, 1.0f + __expf(-x));
                int   b = k * BLOCK + tid;
                tab[j * 2 * N_BINS + 2 * b    ] = s;
                tab[j * 2 * N_BINS + 2 * b + 1] = s;
            }
        }
    }
    __syncthreads();

    // per-lane copy selector: even lanes -> even words/banks, odd -> odd
    const float* t0 = tab + (tid & 1);
    const float* t1 = t0 + 2 * N_BINS;
    const float* t2 = t0 + 4 * N_BINS;

    const long long nthreads = (long long)GRID * BLOCK;       // 303,104

    #pragma unroll 1
    for (long long g = (long long)blockIdx.x * BLOCK + tid;
         g < N_PAIRS; g += nthreads)
    {
        const long long gA = g;
        const long long gB = g + N_PAIRS;   // < N_GROUPS by construction

        // front-batched: 6 independent LDG.128 (MLP=6), 48B lane stride each
        const int4* ia = idx4 + gA * 3;
        const int4* ib = idx4 + gB * 3;
        int4 a0 = ia[0];
        int4 a1 = ia[1];
        int4 a2 = ia[2];
        int4 b0 = ib[0];
        int4 b1 = ib[1];
        int4 b2 = ib[2];

        float4 rA, rB;
        rA.x = t0[2*a0.x] * t1[2*a0.y] * t2[2*a0.z];
        rA.y = t0[2*a0.w] * t1[2*a1.x] * t2[2*a1.y];
        rA.z = t0[2*a1.z] * t1[2*a1.w] * t2[2*a2.x];
        rA.w = t0[2*a2.y] * t1[2*a2.z] * t2[2*a2.w];
        rB.x = t0[2*b0.x] * t1[2*b0.y] * t2[2*b0.z];
        rB.y = t0[2*b0.w] * t1[2*b1.x] * t2[2*b1.y];
        rB.z = t0[2*b1.z] * t1[2*b1.w] * t2[2*b2.x];
        rB.w = t0[2*b2.y] * t1[2*b2.z] * t2[2*b2.w];

        out4[gA] = rA;
        out4[gB] = rB;
    }
}

extern "C" void kernel_launch(void* const* d_in, const int* in_sizes, int n_in,
                              void* d_out, int out_size)
{
    const float* bin_centers = (const float*)d_in[0];
    const int4*  idx4        = (const int4*) d_in[1];
    const float* lb          = (const float*)d_in[2];
    const float* ub          = (const float*)d_in[3];

    pm_kernel<<<GRID, BLOCK>>>(bin_centers, idx4, lb, ub, (float4*)d_out);
}

// round 15
// speedup vs baseline: 1.3869x; 1.3869x over previous
#include <cuda_runtime.h>
#include <math.h>

// PerformanceModel_4346506903896
// out[i] = prod_j sigmoid( (ub[j] - logit(bin_centers[idx[i][j]])) / (ub[j]-lb[j]+1e-4) )
//
// R15: revert to proven R11 structure (12KB LUT — R14 showed big-smem variants
// starve the L1D carveout and expose latency). Residual micro-opts only:
//   - 32-bit loop/address arithmetic (all offsets < 2^31)
//   - __ldcs for the one-touch index stream, __stcs for the write-once output
// Model: kernel sits on the L1tex wavefront wall (~159 wf / 64 groups).
//
// Inputs (metadata order):
//   d_in[0]: bin_centers  float32 [1024]
//   d_in[1]: indices      int32   [16777216, 3]
//   d_in[2]: lb           float32 [3]
//   d_in[3]: ub           float32 [3]
//   d_in[4]: operator_number (unused by the math)
// Output: float32 [16777216]

#define N_BINS   1024
#define BLOCK    256
#define GRID     1184u                      // 148 SMs x 8 CTAs
#define N_GROUPS 4194304u                   // 16,777,216 rows / 4
#define N_PAIRS  (N_GROUPS / 2u)            // 2,097,152

__global__ __launch_bounds__(BLOCK, 8)
void pm_kernel(const float* __restrict__ bin_centers,
               const int4*  __restrict__ idx4,
               const float* __restrict__ lb,
               const float* __restrict__ ub,
               float4*      __restrict__ out4)
{
    __shared__ float tab[3 * N_BINS];       // 12 KB: tab[j*1024 + b]

    const unsigned tid = threadIdx.x;

    // ---- LUT init: 4 logits/thread, 12 sigmoid entries/thread, all MUFU ----
    {
        float lg[4];
        #pragma unroll
        for (int k = 0; k < 4; ++k) {
            float c = bin_centers[k * BLOCK + tid];
            lg[k] = __logf(__fdividef(c, 1.0f - c));   // finite: c in (0.01,0.99)
        }
        #pragma unroll
        for (int j = 0; j < 3; ++j) {
            float u  = ub[j];
            float iv = __fdividef(1.0f, u - lb[j] + 1e-4f);
            #pragma unroll
            for (int k = 0; k < 4; ++k) {
                float x = (u - lg[k]) * iv;
                tab[j * N_BINS + k * BLOCK + tid] =
                    __fdividef(1.0f, 1.0f + __expf(-x));
            }
        }
    }
    __syncthreads();

    const float* t0 = tab;
    const float* t1 = tab + N_BINS;
    const float* t2 = tab + 2 * N_BINS;

    const unsigned nthreads = GRID * BLOCK;             // 303,104

    #pragma unroll 1
    for (unsigned g = blockIdx.x * BLOCK + tid; g < N_PAIRS; g += nthreads)
    {
        const unsigned gA = g;
        const unsigned gB = g + N_PAIRS;    // < N_GROUPS by construction

        // front-batched: 6 independent LDG.128 (MLP=6), 48B lane stride,
        // streaming (evict-first) — indices are touched exactly once.
        const int4* ia = idx4 + gA * 3u;
        const int4* ib = idx4 + gB * 3u;
        int4 a0 = __ldcs(ia + 0);
        int4 a1 = __ldcs(ia + 1);
        int4 a2 = __ldcs(ia + 2);
        int4 b0 = __ldcs(ib + 0);
        int4 b1 = __ldcs(ib + 1);
        int4 b2 = __ldcs(ib + 2);

        float4 rA, rB;
        rA.x = t0[a0.x] * t1[a0.y] * t2[a0.z];
        rA.y = t0[a0.w] * t1[a1.x] * t2[a1.y];
        rA.z = t0[a1.z] * t1[a1.w] * t2[a2.x];
        rA.w = t0[a2.y] * t1[a2.z] * t2[a2.w];
        rB.x = t0[b0.x] * t1[b0.y] * t2[b0.z];
        rB.y = t0[b0.w] * t1[b1.x] * t2[b1.y];
        rB.z = t0[b1.z] * t1[b1.w] * t2[b2.x];
        rB.w = t0[b2.y] * t1[b2.z] * t2[b2.w];

        __stcs(out4 + gA, rA);              // write-once output, evict-first
        __stcs(out4 + gB, rB);
    }
}

extern "C" void kernel_launch(void* const* d_in, const int* in_sizes, int n_in,
                              void* d_out, int out_size)
{
    const float* bin_centers = (const float*)d_in[0];
    const int4*  idx4        = (const int4*) d_in[1];
    const float* lb          = (const float*)d_in[2];
    const float* ub          = (const float*)d_in[3];

    pm_kernel<<<GRID, BLOCK>>>(bin_centers, idx4, lb, ub, (float4*)d_out);
}

// round 16
// speedup vs baseline: 1.3947x; 1.0056x over previous
#include <cuda_runtime.h>
#include <math.h>
#include <stdint.h>

// PerformanceModel_4346506903896
// out[i] = prod_j sigmoid( (ub[j] - logit(bin_centers[idx[i][j]])) / (ub[j]-lb[j]+1e-4) )
//
// R16: replace mainloop index LDGs with 1D TMA bulk copies (cp.async.bulk)
// into a 2-stage smem ring. The TMA engine delivers GMEM->SMEM without LDG
// wavefronts; readback is LDS.128 at 48B/thread stride == provably bank-
// conflict-free. L1tex budget per 256 rows: 159 wf -> ~111 wf (-30%).
// No mainloop LDG => L1D carveout squeeze (R14 failure mode) is irrelevant.
//   - 512 CTAs x 256 thr; each CTA consumes exactly 32 chunks of 12KB
//     (256 groups x 48B). 16384 chunks total = 4,194,304 groups. No tails.
//   - smem: 12KB LUT + 2x12KB ring + 2 mbarriers = 36.9KB (6 CTAs/SM).
//
// Inputs (metadata order):
//   d_in[0]: bin_centers  float32 [1024]
//   d_in[1]: indices      int32   [16777216, 3]
//   d_in[2]: lb           float32 [3]
//   d_in[3]: ub           float32 [3]
//   d_in[4]: operator_number (unused by the math)
// Output: float32 [16777216]

#define N_BINS        1024
#define BLOCK         256
#define GRID          512
#define CHUNK_BYTES   12288u               // 256 threads * 48B
#define CHUNKS_PER_CTA 32
#define GROUPS_PER_CHUNK 256u

__device__ __forceinline__ uint32_t smem_u32(const void* p) {
    return (uint32_t)__cvta_generic_to_shared(p);
}

__device__ __forceinline__ void mbar_init(uint32_t mbar, uint32_t count) {
    asm volatile("mbarrier.init.shared.b64 [%0], %1;"
                 :: "r"(mbar), "r"(count) : "memory");
}

__device__ __forceinline__ void mbar_expect_tx(uint32_t mbar, uint32_t bytes) {
    asm volatile("mbarrier.arrive.expect_tx.shared.b64 _, [%0], %1;"
                 :: "r"(mbar), "r"(bytes) : "memory");
}

__device__ __forceinline__ void tma_bulk_g2s(uint32_t dst_smem,
                                             const void* src_gmem,
                                             uint32_t bytes, uint32_t mbar) {
    asm volatile(
        "cp.async.bulk.shared::cluster.global.mbarrier::complete_tx::bytes "
        "[%0], [%1], %2, [%3];"
        :: "r"(dst_smem), "l"(src_gmem), "r"(bytes), "r"(mbar) : "memory");
}

__device__ __forceinline__ void mbar_wait_parity(uint32_t mbar, uint32_t parity) {
    uint32_t done;
    asm volatile(
        "{\n\t.reg .pred p;\n\t"
        "mbarrier.try_wait.parity.acquire.cta.shared::cta.b64 p, [%1], %2;\n\t"
        "selp.b32 %0, 1, 0, p;\n\t}"
        : "=r"(done) : "r"(mbar), "r"(parity) : "memory");
    if (!done) {
        asm volatile(
            "{\n\t.reg .pred P1;\n\t"
            "WAIT_LOOP_%=:\n\t"
            "mbarrier.try_wait.parity.acquire.cta.shared::cta.b64 P1, [%0], %1, 0x989680;\n\t"
            "@P1 bra.uni WAIT_DONE_%=;\n\t"
            "bra.uni WAIT_LOOP_%=;\n\t"
            "WAIT_DONE_%=:\n\t}"
            :: "r"(mbar), "r"(parity) : "memory");
    }
}

__global__ __launch_bounds__(BLOCK)
void pm_kernel(const float* __restrict__ bin_centers,
               const char*  __restrict__ idx_bytes,   // index array as bytes
               const float* __restrict__ lb,
               const float* __restrict__ ub,
               float4*      __restrict__ out4)
{
    __shared__ float tab[3 * N_BINS];                       // 12 KB
    __shared__ __align__(128) char stage[2][CHUNK_BYTES];   // 24 KB ring
    __shared__ __align__(8) unsigned long long mbar_s[2];

    const unsigned tid = threadIdx.x;
    const uint32_t mb0 = smem_u32(&mbar_s[0]);
    const uint32_t mb1 = smem_u32(&mbar_s[1]);

    // CTA's contiguous span: chunks [blockIdx.x*32, +32)
    const char* src_base = idx_bytes + (size_t)blockIdx.x * CHUNKS_PER_CTA * CHUNK_BYTES;

    // ---- tid 0: init barriers, prefetch chunks 0 and 1 (overlaps LUT init) --
    if (tid == 0) {
        mbar_init(mb0, 1);
        mbar_init(mb1, 1);
        asm volatile("fence.proxy.async.shared::cta;" ::: "memory");
        mbar_expect_tx(mb0, CHUNK_BYTES);
        tma_bulk_g2s(smem_u32(stage[0]), src_base, CHUNK_BYTES, mb0);
        mbar_expect_tx(mb1, CHUNK_BYTES);
        tma_bulk_g2s(smem_u32(stage[1]), src_base + CHUNK_BYTES, CHUNK_BYTES, mb1);
    }

    // ---- LUT init: 4 logits/thread, 12 sigmoid entries/thread, all MUFU ----
    {
        float lg[4];
        #pragma unroll
        for (int k = 0; k < 4; ++k) {
            float c = bin_centers[k * BLOCK + tid];
            lg[k] = __logf(__fdividef(c, 1.0f - c));   // finite: c in (0.01,0.99)
        }
        #pragma unroll
        for (int j = 0; j < 3; ++j) {
            float u  = ub[j];
            float iv = __fdividef(1.0f, u - lb[j] + 1e-4f);
            #pragma unroll
            for (int k = 0; k < 4; ++k) {
                float x = (u - lg[k]) * iv;
                tab[j * N_BINS + k * BLOCK + tid] =
                    __fdividef(1.0f, 1.0f + __expf(-x));
            }
        }
    }
    __syncthreads();   // orders mbarrier init before any consumer wait

    const float* t0 = tab;
    const float* t1 = tab + N_BINS;
    const float* t2 = tab + 2 * N_BINS;

    // first output group of this CTA
    unsigned out_g = blockIdx.x * (CHUNKS_PER_CTA * GROUPS_PER_CHUNK) + tid;

    #pragma unroll 1
    for (int i = 0; i < CHUNKS_PER_CTA; ++i) {
        const int      s      = i & 1;
        const uint32_t parity = (unsigned)(i >> 1) & 1u;
        mbar_wait_parity(s ? mb1 : mb0, parity);

        // conflict-free readback: 3x LDS.128 at 48B/thread stride
        const int4* my = (const int4*)(stage[s] + tid * 48u);
        int4 a = my[0];
        int4 b = my[1];
        int4 c = my[2];

        float4 r;
        r.x = t0[a.x] * t1[a.y] * t2[a.z];
        r.y = t0[a.w] * t1[b.x] * t2[b.y];
        r.z = t0[b.z] * t1[b.w] * t2[c.x];
        r.w = t0[c.y] * t1[c.z] * t2[c.w];

        __stcs(out4 + out_g, r);           // write-once output, evict-first
        out_g += GROUPS_PER_CHUNK;

        __syncthreads();                   // all lanes done reading stage s

        if (tid == 0 && i + 2 < CHUNKS_PER_CTA) {
            const uint32_t mb = s ? mb1 : mb0;
            mbar_expect_tx(mb, CHUNK_BYTES);
            tma_bulk_g2s(smem_u32(stage[s]),
                         src_base + (size_t)(i + 2) * CHUNK_BYTES,
                         CHUNK_BYTES, mb);
        }
    }
}

extern "C" void kernel_launch(void* const* d_in, const int* in_sizes, int n_in,
                              void* d_out, int out_size)
{
    const float* bin_centers = (const float*)d_in[0];
    const char*  idx_bytes   = (const char*) d_in[1];
    const float* lb          = (const float*)d_in[2];
    const float* ub          = (const float*)d_in[3];

    pm_kernel<<<GRID, BLOCK>>>(bin_centers, idx_bytes, lb, ub, (float4*)d_out);
}